// round 17
// baseline (speedup 1.0000x reference)
#include <cuda_runtime.h>
#include <cuda_bf16.h>

#define W_IN 160
#define H_IN 160
#define HW   (H_IN * W_IN)
#define C_IN 256
#define POOLED 7
#define NBIN  (POOLED * POOLED)
#define MAXT 5                     // full 5x5 window; weights 0-padded
#define BMAX 2
#define NMAX 1024

// 52.4 MB NHWC scratch: g_nhwc[((b*H + y)*W + x)*C + c]
__device__ float g_nhwc[BMAX * HW * C_IN];
// per-(n,bin) precomputed: WX[5], WY[5], inv, base(packed int), pad -> 16 floats
__device__ float g_wt[NMAX * NBIN * 16];

// ------------- kernel 0: per-(n,bin) geometry + separable weights ------------
__global__ __launch_bounds__(256)
void weights_kernel(const float* __restrict__ rois,
                    const float* __restrict__ offset,
                    int total)
{
    const int idx = blockIdx.x * 256 + threadIdx.x;
    if (idx >= total) return;
    const int n   = idx / NBIN;
    const int bin = idx - n * NBIN;
    const int ph  = bin / POOLED;
    const int pw  = bin - ph * POOLED;

    const float* roi = rois + n * 5;
    const int   b  = (int)roi[0];
    const float rsw = rintf(roi[1]) * 0.0625f - 0.5f;
    const float rsh = rintf(roi[2]) * 0.0625f - 0.5f;
    const float rew = (rintf(roi[3]) + 1.0f) * 0.0625f - 0.5f;
    const float reh = (rintf(roi[4]) + 1.0f) * 0.0625f - 0.5f;
    const float rw  = fmaxf(rew - rsw, 0.1f);
    const float rh  = fmaxf(reh - rsh, 0.1f);
    const float bw  = rw * (1.0f / 7.0f);
    const float bh  = rh * (1.0f / 7.0f);
    const float sw  = bw * 0.25f;
    const float sh  = bh * 0.25f;

    const float tx = offset[((n * 2 + 0) * POOLED + ph) * POOLED + pw] * 0.1f;
    const float ty = offset[((n * 2 + 1) * POOLED + ph) * POOLED + pw] * 0.1f;

    const float wstart = pw * bw + rsw + tx * rw;
    const float hstart = ph * bh + rsh + ty * rh;

    // 5x5 window base, clamped fully in-image
    const float xcA = fminf(fmaxf(wstart, 0.0f), (float)(W_IN - 1));
    const float ycA = fminf(fmaxf(hstart, 0.0f), (float)(H_IN - 1));
    const int xlo = min((int)floorf(xcA), W_IN - MAXT);
    const int ylo = min((int)floorf(ycA), H_IN - MAXT);

    // separable accumulated weights over the 5 anchors; hat(d)=max(0,1-|d|)
    // reproduces floor/ceil bilinear splitting exactly. Anchors w/o support -> 0.
    float WX[MAXT], WY[MAXT];
    #pragma unroll
    for (int e = 0; e < MAXT; e++) { WX[e] = 0.0f; WY[e] = 0.0f; }
    float cntX = 0.0f, cntY = 0.0f;
    #pragma unroll
    for (int s = 0; s < 4; s++) {
        const float x   = wstart + (float)s * sw;
        const float okx = (x >= -0.5f && x <= (float)W_IN - 0.5f) ? 1.0f : 0.0f;
        const float xc  = fminf(fmaxf(x, 0.0f), (float)(W_IN - 1));
        cntX += okx;
        #pragma unroll
        for (int e = 0; e < MAXT; e++)
            WX[e] += okx * fmaxf(1.0f - fabsf(xc - (float)(xlo + e)), 0.0f);

        const float y   = hstart + (float)s * sh;
        const float oky = (y >= -0.5f && y <= (float)H_IN - 0.5f) ? 1.0f : 0.0f;
        const float yc  = fminf(fmaxf(y, 0.0f), (float)(H_IN - 1));
        cntY += oky;
        #pragma unroll
        for (int e = 0; e < MAXT; e++)
            WY[e] += oky * fmaxf(1.0f - fabsf(yc - (float)(ylo + e)), 0.0f);
    }

    float* wt = g_wt + (size_t)idx * 16;
    #pragma unroll
    for (int e = 0; e < MAXT; e++) { wt[e] = WX[e]; wt[5 + e] = WY[e]; }
    wt[10] = 1.0f / fmaxf(cntX * cntY, 1.0f);
    wt[11] = __int_as_float((b * H_IN + ylo) * W_IN + xlo);
}

// ------------- kernel 1: NCHW -> NHWC transpose, 4 y-rows/block, MLP=4 -------
__global__ __launch_bounds__(256, 8)
void nchw_to_nhwc_kernel(const float* __restrict__ in)
{
    __shared__ float t[4][32][33];

    const int xt = blockIdx.x * 32;
    const int y0 = blockIdx.y * 4;
    const int bz = blockIdx.z;
    const int b  = bz >> 3;
    const int c0 = (bz & 7) * 32;
    const int tx = threadIdx.x;              // 0..7
    const int ty = threadIdx.y;              // 0..31

    const float* ip = in + (((size_t)b * C_IN + c0 + ty) * H_IN + y0) * W_IN + xt + 4 * tx;
    float4 v[4];
    #pragma unroll
    for (int j = 0; j < 4; j++)
        v[j] = *(const float4*)(ip + (size_t)j * W_IN);
    #pragma unroll
    for (int j = 0; j < 4; j++) {
        t[j][ty][4 * tx + 0] = v[j].x;
        t[j][ty][4 * tx + 1] = v[j].y;
        t[j][ty][4 * tx + 2] = v[j].z;
        t[j][ty][4 * tx + 3] = v[j].w;
    }
    __syncthreads();

    #pragma unroll
    for (int j = 0; j < 4; j++) {
        float4 o;
        o.x = t[j][4 * tx + 0][ty];
        o.y = t[j][4 * tx + 1][ty];
        o.z = t[j][4 * tx + 2][ty];
        o.w = t[j][4 * tx + 3][ty];
        *(float4*)(g_nhwc
            + (((size_t)b * H_IN + y0 + j) * W_IN + xt + ty) * C_IN + c0 + 4 * tx) = o;
    }
}

// ------------- kernel 2: lean predicated gather (weights precomputed) --------
__global__ __launch_bounds__(256, 6)
void dcnv2_pool_kernel(float* __restrict__ out, int N)
{
    const int group = threadIdx.x >> 6;      // 0..3 -> bin within block
    const int t64   = threadIdx.x & 63;      // channels 4*t64..
    const int bin   = blockIdx.x * 4 + group;
    if (bin >= NBIN) return;
    const int n  = blockIdx.y;

    // uniform per-group parameters (L1-broadcast loads)
    const float* wt = g_wt + (size_t)(n * NBIN + bin) * 16;
    float WX[MAXT], WY[MAXT];
    #pragma unroll
    for (int e = 0; e < MAXT; e++) {
        WX[e] = __ldg(&wt[e]);
        WY[e] = __ldg(&wt[5 + e]);
    }
    const float inv  = __ldg(&wt[10]);
    const int   base = __float_as_int(__ldg(&wt[11]));

    bool px[MAXT], py[MAXT];
    #pragma unroll
    for (int e = 0; e < MAXT; e++) { px[e] = (WX[e] != 0.0f); py[e] = (WY[e] != 0.0f); }

    // predicated gather: 25 independent @P LDG.128 (uniform predicate, no branch)
    const float4* basep = (const float4*)(g_nhwc + (size_t)base * C_IN) + t64;
    float a0 = 0.0f, a1 = 0.0f, a2 = 0.0f, a3 = 0.0f;
    #pragma unroll
    for (int yy = 0; yy < MAXT; yy++) {
        float r0 = 0.0f, r1 = 0.0f, r2 = 0.0f, r3 = 0.0f;
        #pragma unroll
        for (int xx = 0; xx < MAXT; xx++) {
            float4 v = make_float4(0.0f, 0.0f, 0.0f, 0.0f);
            if (px[xx] && py[yy])
                v = __ldg(&basep[(size_t)(yy * W_IN + xx) * (C_IN / 4)]);
            r0 += WX[xx] * v.x;
            r1 += WX[xx] * v.y;
            r2 += WX[xx] * v.z;
            r3 += WX[xx] * v.w;
        }
        a0 += WY[yy] * r0;
        a1 += WY[yy] * r1;
        a2 += WY[yy] * r2;
        a3 += WY[yy] * r3;
    }

    float* op = out + ((size_t)n * C_IN + 4 * t64) * NBIN + bin;
    op[0 * NBIN] = a0 * inv;
    op[1 * NBIN] = a1 * inv;
    op[2 * NBIN] = a2 * inv;
    op[3 * NBIN] = a3 * inv;
}

extern "C" void kernel_launch(void* const* d_in, const int* in_sizes, int n_in,
                              void* d_out, int out_size)
{
    const float* inp    = (const float*)d_in[0];   // (B, 256, 160, 160) f32
    const float* rois   = (const float*)d_in[1];   // (N, 5) f32
    const float* offset = (const float*)d_in[2];   // (N, 2, 7, 7) f32
    float* out = (float*)d_out;                    // (N, 256, 7, 7) f32

    const int B = in_sizes[0] / (C_IN * HW);       // 2
    const int N = in_sizes[1] / 5;

    // kernel 0: per-(n,bin) weights (tiny; independent of input tensor)
    {
        const int total = N * NBIN;
        weights_kernel<<<(total + 255) / 256, 256>>>(rois, offset, total);
    }
    // kernel 1: layout transform NCHW -> NHWC
    {
        dim3 grid(W_IN / 32, H_IN / 4, B * (C_IN / 32));   // 5 x 40 x 16
        dim3 block(8, 32);
        nchw_to_nhwc_kernel<<<grid, block>>>(inp);
    }
    // kernel 2: lean gather (ordered after both)
    {
        dim3 grid((NBIN + 3) / 4, N);                      // 13 x N
        dim3 block(256);
        dcnv2_pool_kernel<<<grid, block>>>(out, N);
    }
}